// round 1
// baseline (speedup 1.0000x reference)
#include <cuda_runtime.h>
#include <math.h>

#define HEADS  12
#define DMODEL 768
#define DK     64
#define BATCH  2
#define SLEN   2048
#define MTOT   (BATCH * SLEN)   // 4096

// Scratch (allocation-free rule: __device__ globals)
__device__ float g_qh[BATCH * HEADS * SLEN * DK];
__device__ float g_kh[BATCH * HEADS * SLEN * DK];
__device__ float g_vh[BATCH * HEADS * SLEN * DK];
__device__ float g_concat[MTOT * DMODEL];

// ---------------------------------------------------------------------------
// C = A @ W^T + bias.  A: [M,K] row-major, W: [N,K] row-major, bias: [N].
// 64x64 block tile, 256 threads, 4x4 per thread, BK=16.
// permute==1: write C in [B,H,S,Dk] layout (for head-split projections).
// ---------------------------------------------------------------------------
__global__ __launch_bounds__(256) void sgemm_kernel(
    const float* __restrict__ A, const float* __restrict__ W,
    const float* __restrict__ bias, float* __restrict__ C,
    int K, int permute)
{
    __shared__ float As[16][64];   // [k][m]
    __shared__ float Bs[16][64];   // [k][n]

    const int tid = threadIdx.x;
    const int tx = tid & 15, ty = tid >> 4;
    const int m0 = blockIdx.y << 6, n0 = blockIdx.x << 6;
    const int lr = tid >> 2;          // 0..63
    const int lc = (tid & 3) << 2;    // 0,4,8,12

    float acc[4][4] = {{0.f}};

    for (int k0 = 0; k0 < K; k0 += 16) {
        __syncthreads();
        float4 a = *(const float4*)(A + (size_t)(m0 + lr) * K + k0 + lc);
        As[lc + 0][lr] = a.x; As[lc + 1][lr] = a.y;
        As[lc + 2][lr] = a.z; As[lc + 3][lr] = a.w;
        float4 w = *(const float4*)(W + (size_t)(n0 + lr) * K + k0 + lc);
        Bs[lc + 0][lr] = w.x; Bs[lc + 1][lr] = w.y;
        Bs[lc + 2][lr] = w.z; Bs[lc + 3][lr] = w.w;
        __syncthreads();

        #pragma unroll
        for (int k = 0; k < 16; k++) {
            float ar[4], br[4];
            *(float4*)ar = *(const float4*)&As[k][ty << 2];
            *(float4*)br = *(const float4*)&Bs[k][tx << 2];
            #pragma unroll
            for (int i = 0; i < 4; i++)
                #pragma unroll
                for (int j = 0; j < 4; j++)
                    acc[i][j] = fmaf(ar[i], br[j], acc[i][j]);
        }
    }

    const int col = n0 + (tx << 2);
    float4 bv = *(const float4*)(bias + col);
    const float bb[4] = {bv.x, bv.y, bv.z, bv.w};

    #pragma unroll
    for (int i = 0; i < 4; i++) {
        const int row = m0 + (ty << 2) + i;
        float4 o;
        o.x = acc[i][0] + bb[0];
        o.y = acc[i][1] + bb[1];
        o.z = acc[i][2] + bb[2];
        o.w = acc[i][3] + bb[3];
        if (permute) {
            // row = b*SLEN + s ; col = h*DK + d
            const int b = row >> 11;          // /2048
            const int s = row & (SLEN - 1);
            const int h = col >> 6;           // /64 (constant within block)
            const int d = col & (DK - 1);
            size_t idx = (((size_t)(b * HEADS + h) * SLEN) + s) * DK + d;
            *(float4*)(C + idx) = o;
        } else {
            *(float4*)(C + (size_t)row * DMODEL + col) = o;
        }
    }
}

// ---------------------------------------------------------------------------
// Flash attention: one block = 64 q-rows of one (b,h). 256 threads (16x16),
// each thread owns a 4x4 tile of S/P and of O. Online softmax in registers.
// ---------------------------------------------------------------------------
__global__ __launch_bounds__(256) void attn_kernel(
    const float* __restrict__ qh, const float* __restrict__ kh,
    const float* __restrict__ vh, float* __restrict__ concat)
{
    extern __shared__ float sm[];
    float* Qs = sm;           // [DK][64] : Qs[d*64 + r]
    float* Ks = sm + 4096;    // [DK][64] : Ks[d*64 + c]
    float* Vs = sm + 8192;    // [64][DK] : Vs[kv*64 + d]
    float* Ps = sm + 12288;   // [64][64] : Ps[r*64 + kv]

    const int tid = threadIdx.x;
    const int tx = tid & 15, ty = tid >> 4;
    const int nq = SLEN / 64;                 // 32 q tiles
    const int bh = blockIdx.x / nq;
    const int qt = blockIdx.x % nq;
    const int b  = bh / HEADS, h = bh % HEADS;

    const float* Qp = qh + (size_t)bh * SLEN * DK + (size_t)qt * 64 * DK;
    const float* Kp = kh + (size_t)bh * SLEN * DK;
    const float* Vp = vh + (size_t)bh * SLEN * DK;

    const int lr = tid >> 2;          // 0..63 row
    const int lc = (tid & 3) << 4;    // 0,16,32,48

    // Load Q tile transposed into Qs[d][r]
    #pragma unroll
    for (int j = 0; j < 16; j += 4) {
        float4 v = *(const float4*)(Qp + lr * DK + lc + j);
        Qs[(lc + j + 0) * 64 + lr] = v.x;
        Qs[(lc + j + 1) * 64 + lr] = v.y;
        Qs[(lc + j + 2) * 64 + lr] = v.z;
        Qs[(lc + j + 3) * 64 + lr] = v.w;
    }

    float m_i[4], l_i[4], O[4][4];
    #pragma unroll
    for (int i = 0; i < 4; i++) {
        m_i[i] = -1e30f; l_i[i] = 0.f;
        #pragma unroll
        for (int j = 0; j < 4; j++) O[i][j] = 0.f;
    }

    const float scale = 0.125f;  // 1/sqrt(64)

    for (int kt = 0; kt < SLEN / 64; kt++) {
        __syncthreads();  // previous iter's Ks/Vs/Ps reads complete
        {
            const float* kb = Kp + (size_t)kt * 64 * DK;
            const float* vb = Vp + (size_t)kt * 64 * DK;
            #pragma unroll
            for (int j = 0; j < 16; j += 4) {
                float4 v = *(const float4*)(kb + lr * DK + lc + j);
                Ks[(lc + j + 0) * 64 + lr] = v.x;
                Ks[(lc + j + 1) * 64 + lr] = v.y;
                Ks[(lc + j + 2) * 64 + lr] = v.z;
                Ks[(lc + j + 3) * 64 + lr] = v.w;
                float4 w = *(const float4*)(vb + lr * DK + lc + j);
                *(float4*)&Vs[lr * DK + lc + j] = w;
            }
        }
        __syncthreads();

        // S = scale * Q @ K^T   (4x4 per thread)
        float Sa[4][4] = {{0.f}};
        #pragma unroll
        for (int d = 0; d < DK; d++) {
            float qr[4], kr[4];
            *(float4*)qr = *(const float4*)&Qs[d * 64 + (ty << 2)];
            *(float4*)kr = *(const float4*)&Ks[d * 64 + (tx << 2)];
            #pragma unroll
            for (int i = 0; i < 4; i++)
                #pragma unroll
                for (int j = 0; j < 4; j++)
                    Sa[i][j] = fmaf(qr[i], kr[j], Sa[i][j]);
        }
        #pragma unroll
        for (int i = 0; i < 4; i++)
            #pragma unroll
            for (int j = 0; j < 4; j++)
                Sa[i][j] *= scale;

        // Online softmax: row max across 16 tx lanes
        float rmax[4], fsc[4], rsum[4];
        #pragma unroll
        for (int i = 0; i < 4; i++) {
            rmax[i] = fmaxf(fmaxf(Sa[i][0], Sa[i][1]), fmaxf(Sa[i][2], Sa[i][3]));
            #pragma unroll
            for (int msk = 8; msk; msk >>= 1)
                rmax[i] = fmaxf(rmax[i], __shfl_xor_sync(0xffffffffu, rmax[i], msk));
            float nm = fmaxf(m_i[i], rmax[i]);
            fsc[i] = __expf(m_i[i] - nm);
            m_i[i] = nm;
            rsum[i] = 0.f;
        }
        #pragma unroll
        for (int i = 0; i < 4; i++) {
            float4 pv;
            pv.x = __expf(Sa[i][0] - m_i[i]);
            pv.y = __expf(Sa[i][1] - m_i[i]);
            pv.z = __expf(Sa[i][2] - m_i[i]);
            pv.w = __expf(Sa[i][3] - m_i[i]);
            rsum[i] = pv.x + pv.y + pv.z + pv.w;
            *(float4*)&Ps[((ty << 2) + i) * 64 + (tx << 2)] = pv;
        }
        #pragma unroll
        for (int i = 0; i < 4; i++) {
            #pragma unroll
            for (int msk = 8; msk; msk >>= 1)
                rsum[i] += __shfl_xor_sync(0xffffffffu, rsum[i], msk);
            l_i[i] = l_i[i] * fsc[i] + rsum[i];
            #pragma unroll
            for (int j = 0; j < 4; j++) O[i][j] *= fsc[i];
        }
        __syncthreads();  // Ps visible

        // O += P @ V
        #pragma unroll
        for (int k0 = 0; k0 < 64; k0 += 4) {
            float p4[4][4], v4[4][4];
            #pragma unroll
            for (int i = 0; i < 4; i++)
                *(float4*)p4[i] = *(const float4*)&Ps[((ty << 2) + i) * 64 + k0];
            #pragma unroll
            for (int t = 0; t < 4; t++)
                *(float4*)v4[t] = *(const float4*)&Vs[(k0 + t) * DK + (tx << 2)];
            #pragma unroll
            for (int i = 0; i < 4; i++)
                #pragma unroll
                for (int t = 0; t < 4; t++)
                    #pragma unroll
                    for (int j = 0; j < 4; j++)
                        O[i][j] = fmaf(p4[i][t], v4[t][j], O[i][j]);
        }
    }

    // Normalize and write to concat layout [b, s, h*DK + d]
    #pragma unroll
    for (int i = 0; i < 4; i++) {
        const float inv = 1.f / l_i[i];
        const int srow = qt * 64 + (ty << 2) + i;
        float4 o;
        o.x = O[i][0] * inv; o.y = O[i][1] * inv;
        o.z = O[i][2] * inv; o.w = O[i][3] * inv;
        size_t idx = ((size_t)b * SLEN + srow) * DMODEL + h * DK + (tx << 2);
        *(float4*)(concat + idx) = o;
    }
}

// ---------------------------------------------------------------------------
extern "C" void kernel_launch(void* const* d_in, const int* in_sizes, int n_in,
                              void* d_out, int out_size)
{
    (void)in_sizes; (void)n_in; (void)out_size;
    const float* q  = (const float*)d_in[0];
    const float* k  = (const float*)d_in[1];
    const float* v  = (const float*)d_in[2];
    const float* Wk = (const float*)d_in[3];
    const float* bk = (const float*)d_in[4];
    const float* Wo = (const float*)d_in[5];
    const float* bo = (const float*)d_in[6];
    float* out = (float*)d_out;

    float *qh, *kh, *vh, *concat;
    cudaGetSymbolAddress((void**)&qh, g_qh);
    cudaGetSymbolAddress((void**)&kh, g_kh);
    cudaGetSymbolAddress((void**)&vh, g_vh);
    cudaGetSymbolAddress((void**)&concat, g_concat);

    dim3 g(DMODEL / 64, MTOT / 64);   // (12, 64)

    // Projections (all use Wk/bk per the reference's faithful bug)
    sgemm_kernel<<<g, 256>>>(q, Wk, bk, qh, DMODEL, 1);
    sgemm_kernel<<<g, 256>>>(k, Wk, bk, kh, DMODEL, 1);
    sgemm_kernel<<<g, 256>>>(v, Wk, bk, vh, DMODEL, 1);

    // Attention
    cudaFuncSetAttribute((const void*)attn_kernel,
                         cudaFuncAttributeMaxDynamicSharedMemorySize, 64 * 1024);
    attn_kernel<<<BATCH * HEADS * (SLEN / 64), 256, 64 * 1024>>>(qh, kh, vh, concat);

    // Output projection
    sgemm_kernel<<<g, 256>>>(concat, Wo, bo, out, DMODEL, 0);
}

// round 2
// speedup vs baseline: 3.0696x; 3.0696x over previous
#include <cuda_runtime.h>
#include <stdint.h>
#include <math.h>

#define HEADS  12
#define DMODEL 768
#define DK     64
#define BATCH  2
#define SLEN   2048
#define MTOT   (BATCH * SLEN)   // 4096

__device__ float g_qh[BATCH * HEADS * SLEN * DK];
__device__ float g_kh[BATCH * HEADS * SLEN * DK];
__device__ float g_vh[BATCH * HEADS * SLEN * DK];
__device__ float g_concat[MTOT * DMODEL];

// ---------------------------------------------------------------------------
__device__ __forceinline__ uint32_t f2tf(float x) {
    uint32_t r;
    asm("cvt.rna.tf32.f32 %0, %1;" : "=r"(r) : "f"(x));
    return r;
}

__device__ __forceinline__ void mma8(float* c,
    uint32_t a0, uint32_t a1, uint32_t a2, uint32_t a3,
    uint32_t b0, uint32_t b1)
{
    asm volatile(
        "mma.sync.aligned.m16n8k8.row.col.f32.tf32.tf32.f32 "
        "{%0,%1,%2,%3},{%4,%5,%6,%7},{%8,%9},{%0,%1,%2,%3};"
        : "+f"(c[0]), "+f"(c[1]), "+f"(c[2]), "+f"(c[3])
        : "r"(a0), "r"(a1), "r"(a2), "r"(a3), "r"(b0), "r"(b1));
}

// ---------------------------------------------------------------------------
// C = A @ W^T + bias.  A:[M,768] row-major, W:[N,768] row-major (= col-major B
// operand directly), bias:[N].  Block 128x128, BK=16, 8 warps (4m x 2n).
// permute: write C into [B,H,S,Dk].
// ---------------------------------------------------------------------------
#define BM 128
#define BN 128
#define BK 16
#define AST 136   // As[k][m] m-stride (conflict-free frag loads)
#define BST 20    // Bs[n][k] k-stride (conflict-free frag loads)

__global__ __launch_bounds__(256) void gemm_tf32(
    const float* __restrict__ A, const float* __restrict__ W,
    const float* __restrict__ bias, float* __restrict__ C, int permute)
{
    __shared__ uint32_t As[BK * AST];
    __shared__ uint32_t Bs[BN * BST];

    const int tid  = threadIdx.x;
    const int lane = tid & 31;
    const int wid  = tid >> 5;
    const int g = lane >> 2, q = lane & 3;
    const int wm = wid >> 1, wn = wid & 1;      // 4 x 2 warps
    const int m0 = blockIdx.y * BM, n0 = blockIdx.x * BN;

    float acc[2][8][4];
    #pragma unroll
    for (int im = 0; im < 2; im++)
        #pragma unroll
        for (int j = 0; j < 8; j++)
            #pragma unroll
            for (int t = 0; t < 4; t++) acc[im][j][t] = 0.f;

    const int lrow = tid >> 2;          // 0..63
    const int lc4  = (tid & 3) << 2;    // 0,4,8,12

    for (int k0 = 0; k0 < DMODEL; k0 += BK) {
        __syncthreads();
        #pragma unroll
        for (int p = 0; p < 2; p++) {
            const int row = lrow + p * 64;
            float4 a = *(const float4*)(A + (size_t)(m0 + row) * DMODEL + k0 + lc4);
            As[(lc4 + 0) * AST + row] = f2tf(a.x);
            As[(lc4 + 1) * AST + row] = f2tf(a.y);
            As[(lc4 + 2) * AST + row] = f2tf(a.z);
            As[(lc4 + 3) * AST + row] = f2tf(a.w);
            float4 w = *(const float4*)(W + (size_t)(n0 + row) * DMODEL + k0 + lc4);
            uint4 wu;
            wu.x = f2tf(w.x); wu.y = f2tf(w.y); wu.z = f2tf(w.z); wu.w = f2tf(w.w);
            *(uint4*)(Bs + row * BST + lc4) = wu;
        }
        __syncthreads();

        #pragma unroll
        for (int ks = 0; ks < 2; ks++) {
            const int kk = ks * 8;
            uint32_t af[2][4];
            #pragma unroll
            for (int im = 0; im < 2; im++) {
                const int mb = wm * 32 + im * 16;
                af[im][0] = As[(kk + q) * AST + mb + g];
                af[im][1] = As[(kk + q) * AST + mb + g + 8];
                af[im][2] = As[(kk + q + 4) * AST + mb + g];
                af[im][3] = As[(kk + q + 4) * AST + mb + g + 8];
            }
            #pragma unroll
            for (int j = 0; j < 8; j++) {
                const int nb = wn * 64 + j * 8;
                uint32_t b0 = Bs[(nb + g) * BST + kk + q];
                uint32_t b1 = Bs[(nb + g) * BST + kk + q + 4];
                mma8(acc[0][j], af[0][0], af[0][1], af[0][2], af[0][3], b0, b1);
                mma8(acc[1][j], af[1][0], af[1][1], af[1][2], af[1][3], b0, b1);
            }
        }
    }

    // Epilogue
    #pragma unroll
    for (int im = 0; im < 2; im++) {
        const int row0 = m0 + wm * 32 + im * 16 + g;
        #pragma unroll
        for (int j = 0; j < 8; j++) {
            const int col = n0 + wn * 64 + j * 8 + 2 * q;
            const float b0v = bias[col], b1v = bias[col + 1];
            float2 o0, o1;
            o0.x = acc[im][j][0] + b0v; o0.y = acc[im][j][1] + b1v;
            o1.x = acc[im][j][2] + b0v; o1.y = acc[im][j][3] + b1v;
            if (permute) {
                const int h = col >> 6, d = col & 63;
                const int b0i = row0 >> 11, s0 = row0 & (SLEN - 1);
                size_t i0 = (((size_t)(b0i * HEADS + h) * SLEN) + s0) * DK + d;
                *(float2*)(C + i0) = o0;
                const int row1 = row0 + 8;
                const int b1i = row1 >> 11, s1 = row1 & (SLEN - 1);
                size_t i1 = (((size_t)(b1i * HEADS + h) * SLEN) + s1) * DK + d;
                *(float2*)(C + i1) = o1;
            } else {
                *(float2*)(C + (size_t)row0 * DMODEL + col) = o0;
                *(float2*)(C + (size_t)(row0 + 8) * DMODEL + col) = o1;
            }
        }
    }
}

// ---------------------------------------------------------------------------
// Flash attention with tf32 mma. Block = 128 q-rows of one (b,h); 8 warps,
// each warp owns 16 q-rows. KV tiles of 64 streamed through smem.
// ---------------------------------------------------------------------------
#define QST 68   // Qs/Ks/Ps row stride (words)
#define VST 72   // Vs row stride

#define OFF_K 8704            // 128*68
#define OFF_V 13056           // + 64*68
#define OFF_P 17664           // + 64*72
#define SM_WORDS 26368        // + 8*16*68
#define SM_BYTES (SM_WORDS * 4)

__global__ __launch_bounds__(256) void attn_tf32(
    const float* __restrict__ qh, const float* __restrict__ kh,
    const float* __restrict__ vh, float* __restrict__ concat)
{
    extern __shared__ uint32_t sm[];
    uint32_t* Qs = sm;
    uint32_t* Ks = sm + OFF_K;
    uint32_t* Vs = sm + OFF_V;
    uint32_t* Ps = sm + OFF_P;

    const int tid  = threadIdx.x;
    const int lane = tid & 31;
    const int w    = tid >> 5;
    const int g = lane >> 2, q = lane & 3;
    const int qt = blockIdx.x, bh = blockIdx.y;
    const int b = bh / HEADS, h = bh % HEADS;

    const float* Qp = qh + ((size_t)bh * SLEN + qt * 128) * DK;
    const float* Kp = kh + (size_t)bh * SLEN * DK;
    const float* Vp = vh + (size_t)bh * SLEN * DK;

    // Load Q (scaled by 1/8 = 1/sqrt(Dk), exact) as tf32
    #pragma unroll
    for (int p = 0; p < 8; p++) {
        const int idx = tid + p * 256;
        const int row = idx >> 4, c4 = (idx & 15) << 2;
        float4 v = *(const float4*)(Qp + row * DK + c4);
        uint4 u;
        u.x = f2tf(v.x * 0.125f); u.y = f2tf(v.y * 0.125f);
        u.z = f2tf(v.z * 0.125f); u.w = f2tf(v.w * 0.125f);
        *(uint4*)(Qs + row * QST + c4) = u;
    }

    float O[8][4];
    #pragma unroll
    for (int j = 0; j < 8; j++)
        #pragma unroll
        for (int t = 0; t < 4; t++) O[j][t] = 0.f;
    float m0r = -1e30f, m1r = -1e30f, l0r = 0.f, l1r = 0.f;

    uint32_t* Pw = Ps + w * 16 * QST;
    const int mb = w * 16;

    for (int kt = 0; kt < SLEN / 64; kt++) {
        __syncthreads();
        const float* kb = Kp + (size_t)kt * 64 * DK;
        const float* vb = Vp + (size_t)kt * 64 * DK;
        #pragma unroll
        for (int p = 0; p < 4; p++) {
            const int idx = tid + p * 256;
            const int row = idx >> 4, c4 = (idx & 15) << 2;
            float4 kv = *(const float4*)(kb + row * DK + c4);
            uint4 ku;
            ku.x = f2tf(kv.x); ku.y = f2tf(kv.y); ku.z = f2tf(kv.z); ku.w = f2tf(kv.w);
            *(uint4*)(Ks + row * QST + c4) = ku;
            float4 vv = *(const float4*)(vb + row * DK + c4);
            uint4 vu;
            vu.x = f2tf(vv.x); vu.y = f2tf(vv.y); vu.z = f2tf(vv.z); vu.w = f2tf(vv.w);
            *(uint4*)(Vs + row * VST + c4) = vu;
        }
        __syncthreads();

        // S = (Q/8) @ K^T  : 8 n-frags of m16n8
        float S[8][4];
        #pragma unroll
        for (int j = 0; j < 8; j++)
            #pragma unroll
            for (int t = 0; t < 4; t++) S[j][t] = 0.f;
        #pragma unroll
        for (int ks = 0; ks < 8; ks++) {
            const int kk = ks * 8;
            uint32_t a0 = Qs[(mb + g) * QST + kk + q];
            uint32_t a1 = Qs[(mb + g + 8) * QST + kk + q];
            uint32_t a2 = Qs[(mb + g) * QST + kk + q + 4];
            uint32_t a3 = Qs[(mb + g + 8) * QST + kk + q + 4];
            #pragma unroll
            for (int j = 0; j < 8; j++) {
                uint32_t b0 = Ks[(j * 8 + g) * QST + kk + q];
                uint32_t b1 = Ks[(j * 8 + g) * QST + kk + q + 4];
                mma8(S[j], a0, a1, a2, a3, b0, b1);
            }
        }

        // Online softmax. Thread covers rows (mb+g) [S[j][0..1]] and (mb+g+8)
        // [S[j][2..3]]; a row lives on the 4 lanes of one quad -> shfl xor 1,2.
        float mx0 = -1e30f, mx1 = -1e30f;
        #pragma unroll
        for (int j = 0; j < 8; j++) {
            mx0 = fmaxf(mx0, fmaxf(S[j][0], S[j][1]));
            mx1 = fmaxf(mx1, fmaxf(S[j][2], S[j][3]));
        }
        mx0 = fmaxf(mx0, __shfl_xor_sync(0xffffffffu, mx0, 1));
        mx0 = fmaxf(mx0, __shfl_xor_sync(0xffffffffu, mx0, 2));
        mx1 = fmaxf(mx1, __shfl_xor_sync(0xffffffffu, mx1, 1));
        mx1 = fmaxf(mx1, __shfl_xor_sync(0xffffffffu, mx1, 2));

        const float nm0 = fmaxf(m0r, mx0), nm1 = fmaxf(m1r, mx1);
        const float f0 = __expf(m0r - nm0), f1 = __expf(m1r - nm1);
        m0r = nm0; m1r = nm1;

        float s0 = 0.f, s1 = 0.f;
        #pragma unroll
        for (int j = 0; j < 8; j++) {
            const float e0 = __expf(S[j][0] - nm0);
            const float e1 = __expf(S[j][1] - nm0);
            const float e2 = __expf(S[j][2] - nm1);
            const float e3 = __expf(S[j][3] - nm1);
            s0 += e0 + e1; s1 += e2 + e3;
            uint2 p01, p23;
            p01.x = f2tf(e0); p01.y = f2tf(e1);
            p23.x = f2tf(e2); p23.y = f2tf(e3);
            *(uint2*)(Pw + g * QST + j * 8 + 2 * q) = p01;
            *(uint2*)(Pw + (g + 8) * QST + j * 8 + 2 * q) = p23;
        }
        s0 += __shfl_xor_sync(0xffffffffu, s0, 1);
        s0 += __shfl_xor_sync(0xffffffffu, s0, 2);
        s1 += __shfl_xor_sync(0xffffffffu, s1, 1);
        s1 += __shfl_xor_sync(0xffffffffu, s1, 2);
        l0r = l0r * f0 + s0;
        l1r = l1r * f1 + s1;
        #pragma unroll
        for (int j = 0; j < 8; j++) {
            O[j][0] *= f0; O[j][1] *= f0;
            O[j][2] *= f1; O[j][3] *= f1;
        }
        __syncwarp();

        // O += P @ V
        #pragma unroll
        for (int ks = 0; ks < 8; ks++) {
            const int kk = ks * 8;
            uint32_t a0 = Pw[g * QST + kk + q];
            uint32_t a1 = Pw[(g + 8) * QST + kk + q];
            uint32_t a2 = Pw[g * QST + kk + q + 4];
            uint32_t a3 = Pw[(g + 8) * QST + kk + q + 4];
            #pragma unroll
            for (int j = 0; j < 8; j++) {
                uint32_t b0 = Vs[(kk + q) * VST + j * 8 + g];
                uint32_t b1 = Vs[(kk + q + 4) * VST + j * 8 + g];
                mma8(O[j], a0, a1, a2, a3, b0, b1);
            }
        }
    }

    // Normalize + write to concat [b][s][h*64+d]
    const float inv0 = 1.f / l0r, inv1 = 1.f / l1r;
    const int srow = qt * 128 + w * 16 + g;
    const size_t base0 = ((size_t)b * SLEN + srow) * DMODEL + h * 64;
    const size_t base1 = base0 + (size_t)8 * DMODEL;
    #pragma unroll
    for (int j = 0; j < 8; j++) {
        float2 o0, o1;
        o0.x = O[j][0] * inv0; o0.y = O[j][1] * inv0;
        o1.x = O[j][2] * inv1; o1.y = O[j][3] * inv1;
        *(float2*)(concat + base0 + j * 8 + 2 * q) = o0;
        *(float2*)(concat + base1 + j * 8 + 2 * q) = o1;
    }
}

// ---------------------------------------------------------------------------
extern "C" void kernel_launch(void* const* d_in, const int* in_sizes, int n_in,
                              void* d_out, int out_size)
{
    (void)in_sizes; (void)n_in; (void)out_size;
    const float* q  = (const float*)d_in[0];
    const float* k  = (const float*)d_in[1];
    const float* v  = (const float*)d_in[2];
    const float* Wk = (const float*)d_in[3];
    const float* bk = (const float*)d_in[4];
    const float* Wo = (const float*)d_in[5];
    const float* bo = (const float*)d_in[6];
    float* out = (float*)d_out;

    float *qh, *kh, *vh, *concat;
    cudaGetSymbolAddress((void**)&qh, g_qh);
    cudaGetSymbolAddress((void**)&kh, g_kh);
    cudaGetSymbolAddress((void**)&vh, g_vh);
    cudaGetSymbolAddress((void**)&concat, g_concat);

    dim3 gg(DMODEL / BN, MTOT / BM);   // (6, 32)

    gemm_tf32<<<gg, 256>>>(q, Wk, bk, qh, 1);
    gemm_tf32<<<gg, 256>>>(k, Wk, bk, kh, 1);
    gemm_tf32<<<gg, 256>>>(v, Wk, bk, vh, 1);

    cudaFuncSetAttribute((const void*)attn_tf32,
                         cudaFuncAttributeMaxDynamicSharedMemorySize, SM_BYTES);
    attn_tf32<<<dim3(SLEN / 128, BATCH * HEADS), 256, SM_BYTES>>>(qh, kh, vh, concat);

    gemm_tf32<<<gg, 256>>>(concat, Wo, bo, out, 0);
}